// round 3
// baseline (speedup 1.0000x reference)
#include <cuda_runtime.h>
#include <cstdint>

// Problem constants (fixed by reference)
#define BB   16
#define CC   64
#define OHH  128
#define OWW  128
#define KK   4
#define PP   4
#define OUT_H 256
#define OUT_W 256

#define IN_PLANE  (OHH * OWW)        // 16384
#define OUT_PLANE (OUT_H * OUT_W)    // 65536
#define N_ELEMS   (BB * CC * IN_PLANE)       // 16,777,216
#define OUT_ELEMS (BB * CC * OUT_PLANE)      // 67,108,864

__global__ void zero_out_kernel(float4* __restrict__ out, int n4) {
    int i = blockIdx.x * blockDim.x + threadIdx.x;
    int stride = gridDim.x * blockDim.x;
    float4 z = make_float4(0.f, 0.f, 0.f, 0.f);
    for (; i < n4; i += stride) out[i] = z;
}

__global__ void __launch_bounds__(256)
unpool_scatter_kernel(const float* __restrict__ x,
                      const int*   __restrict__ mask,   // int32 (harness-staged)
                      const int4*  __restrict__ smap,   // (OH,OW,K,P) int32, one int4 per (s,k)
                      const float4* __restrict__ wts,   // (OH,OW,K,P) f32, one float4 per (s,k)
                      float* __restrict__ out)
{
    int tid = blockIdx.x * blockDim.x + threadIdx.x;
    if (tid >= N_ELEMS) return;

    int s     = tid & (IN_PLANE - 1);   // oh*OW + ow
    int plane = tid >> 14;              // b*C + c

    float v = __ldg(x + tid);
    int   k = __ldg(mask + tid);        // in [0,4)

    // (s*K + k) selects the P=4 taps: one int4 / float4 each, 16B-aligned
    int mk = (s << 2) + k;
    int4   i4 = __ldg(smap + mk);
    float4 w  = __ldg(wts + mk);

    float* op = out + (size_t)plane * OUT_PLANE;
    atomicAdd(op + i4.x, w.x * v);
    atomicAdd(op + i4.y, w.y * v);
    atomicAdd(op + i4.z, w.z * v);
    atomicAdd(op + i4.w, w.w * v);
}

extern "C" void kernel_launch(void* const* d_in, const int* in_sizes, int n_in,
                              void* d_out, int out_size)
{
    const float*  x    = (const float*)d_in[0];
    const int*    mask = (const int*)d_in[1];
    const int4*   smap = (const int4*)d_in[2];
    const float4* wts  = (const float4*)d_in[3];
    float* out = (float*)d_out;

    // 1) zero the output (poisoned by harness)
    {
        int n4 = OUT_ELEMS / 4;               // 16,777,216 float4s
        zero_out_kernel<<<148 * 32, 256>>>((float4*)out, n4);
    }
    // 2) scatter-add
    {
        int threads = 256;
        int blocks = N_ELEMS / threads;       // 65536
        unpool_scatter_kernel<<<blocks, threads>>>(x, mask, smap, wts, out);
    }
}

// round 4
// speedup vs baseline: 1.0161x; 1.0161x over previous
#include <cuda_runtime.h>
#include <cstdint>

// Problem constants (fixed by reference)
#define BB   16
#define CC   64
#define OHH  128
#define OWW  128
#define KK   4
#define PP   4
#define OUT_H 256
#define OUT_W 256

#define IN_PLANE  (OHH * OWW)        // 16384
#define OUT_PLANE (OUT_H * OUT_W)    // 65536
#define N_ELEMS   (BB * CC * IN_PLANE)       // 16,777,216
#define OUT_ELEMS (BB * CC * OUT_PLANE)      // 67,108,864

__global__ void zero_out_kernel(float4* __restrict__ out, int n4) {
    int i = blockIdx.x * blockDim.x + threadIdx.x;
    int stride = gridDim.x * blockDim.x;
    float4 z = make_float4(0.f, 0.f, 0.f, 0.f);
    for (; i < n4; i += stride) out[i] = z;
}

__global__ void __launch_bounds__(256)
unpool_scatter_kernel(const float* __restrict__ x,
                      const int*   __restrict__ mask,   // int32 (harness-staged)
                      const int4*  __restrict__ smap,   // (OH,OW,K,P) int32, one int4 per (s,k)
                      const float4* __restrict__ wts,   // (OH,OW,K,P) f32, one float4 per (s,k)
                      float* __restrict__ out)
{
    int tid = blockIdx.x * blockDim.x + threadIdx.x;
    if (tid >= N_ELEMS) return;

    int s     = tid & (IN_PLANE - 1);   // oh*OW + ow
    int plane = tid >> 14;              // b*C + c

    float v = __ldg(x + tid);
    int   k = __ldg(mask + tid);        // in [0,4)

    // (s*K + k) selects the P=4 taps: one int4 / float4 each, 16B-aligned
    int mk = (s << 2) + k;
    int4   i4 = __ldg(smap + mk);
    float4 w  = __ldg(wts + mk);

    float* op = out + (size_t)plane * OUT_PLANE;
    atomicAdd(op + i4.x, w.x * v);
    atomicAdd(op + i4.y, w.y * v);
    atomicAdd(op + i4.z, w.z * v);
    atomicAdd(op + i4.w, w.w * v);
}

extern "C" void kernel_launch(void* const* d_in, const int* in_sizes, int n_in,
                              void* d_out, int out_size)
{
    const float*  x    = (const float*)d_in[0];
    const int*    mask = (const int*)d_in[1];
    const int4*   smap = (const int4*)d_in[2];
    const float4* wts  = (const float4*)d_in[3];
    float* out = (float*)d_out;

    // 1) zero the output (poisoned by harness)
    {
        int n4 = OUT_ELEMS / 4;               // 16,777,216 float4s
        zero_out_kernel<<<148 * 32, 256>>>((float4*)out, n4);
    }
    // 2) scatter-add
    {
        int threads = 256;
        int blocks = N_ELEMS / threads;       // 65536
        unpool_scatter_kernel<<<blocks, threads>>>(x, mask, smap, wts, out);
    }
}

// round 5
// speedup vs baseline: 1.0192x; 1.0031x over previous
#include <cuda_runtime.h>
#include <cstdint>

// Problem constants (fixed by reference)
#define BB   16
#define CC   64
#define OHH  128
#define OWW  128
#define KK   4
#define PP   4
#define OUT_H 256
#define OUT_W 256

#define IN_PLANE  (OHH * OWW)        // 16384
#define OUT_PLANE (OUT_H * OUT_W)    // 65536
#define N_ELEMS   (BB * CC * IN_PLANE)       // 16,777,216
#define OUT_ELEMS (BB * CC * OUT_PLANE)      // 67,108,864

__global__ void zero_out_kernel(float4* __restrict__ out, int n4) {
    int i = blockIdx.x * blockDim.x + threadIdx.x;
    int stride = gridDim.x * blockDim.x;
    float4 z = make_float4(0.f, 0.f, 0.f, 0.f);
    for (; i < n4; i += stride) out[i] = z;
}

__global__ void __launch_bounds__(256)
unpool_scatter_kernel(const float* __restrict__ x,
                      const int*   __restrict__ mask,   // int32 (harness-staged)
                      const int4*  __restrict__ smap,   // (OH,OW,K,P) int32, one int4 per (s,k)
                      const float4* __restrict__ wts,   // (OH,OW,K,P) f32, one float4 per (s,k)
                      float* __restrict__ out)
{
    int tid = blockIdx.x * blockDim.x + threadIdx.x;
    if (tid >= N_ELEMS) return;

    int s     = tid & (IN_PLANE - 1);   // oh*OW + ow
    int plane = tid >> 14;              // b*C + c

    float v = __ldg(x + tid);
    int   k = __ldg(mask + tid);        // in [0,4)

    // (s*K + k) selects the P=4 taps: one int4 / float4 each, 16B-aligned
    int mk = (s << 2) + k;
    int4   i4 = __ldg(smap + mk);
    float4 w  = __ldg(wts + mk);

    float* op = out + (size_t)plane * OUT_PLANE;
    atomicAdd(op + i4.x, w.x * v);
    atomicAdd(op + i4.y, w.y * v);
    atomicAdd(op + i4.z, w.z * v);
    atomicAdd(op + i4.w, w.w * v);
}

extern "C" void kernel_launch(void* const* d_in, const int* in_sizes, int n_in,
                              void* d_out, int out_size)
{
    const float*  x    = (const float*)d_in[0];
    const int*    mask = (const int*)d_in[1];
    const int4*   smap = (const int4*)d_in[2];
    const float4* wts  = (const float4*)d_in[3];
    float* out = (float*)d_out;

    // 1) zero the output (poisoned by harness)
    {
        int n4 = OUT_ELEMS / 4;               // 16,777,216 float4s
        zero_out_kernel<<<148 * 32, 256>>>((float4*)out, n4);
    }
    // 2) scatter-add
    {
        int threads = 256;
        int blocks = N_ELEMS / threads;       // 65536
        unpool_scatter_kernel<<<blocks, threads>>>(x, mask, smap, wts, out);
    }
}